// round 4
// baseline (speedup 1.0000x reference)
#include <cuda_runtime.h>
#include <math.h>

#define D      128
#define RREL   500
#define NNODES 200000
#define GRIDB  148
#define TPB    1024
#define NT     (GRIDB * TPB)

// ---------------- device scratch ----------------
__device__ float2 g_acc[NNODES];    // .x = sum(selected·w1), .y = message count
__device__ float  g_w1[D];          // (W_fin @ W_score)[0:D]
__device__ float  g_w2[D];          // (W_fin @ W_score)[D:2D]
__device__ float  g_p[4][D];        // p_x = W_x @ w1
__device__ float  g_bdot[4];        // b_x · w1
__device__ float  g_ceff;           // b_fin·W_score + b_score
__device__ float  g_udot[RREL * 4]; // rel_emb[r] · p_x
__device__ float  g_reldot[RREL];   // rel_emb[r] · w2
__device__ unsigned g_bar;          // monotonic grid-barrier ticket counter

__device__ __forceinline__ float warp_sum(float v) {
#pragma unroll
    for (int o = 16; o > 0; o >>= 1) v += __shfl_down_sync(0xffffffffu, v, o);
    return v;
}

// Monotonic ticket grid barrier: safe across CUDA-graph replays.
__device__ __forceinline__ void grid_barrier() {
    __syncthreads();
    if (threadIdx.x == 0) {
        __threadfence();
        unsigned old = atomicAdd(&g_bar, 1u);
        unsigned target = old - (old % GRIDB) + GRIDB;
        unsigned v;
        do {
            asm volatile("ld.acquire.gpu.u32 %0, [%1];" : "=r"(v) : "l"(&g_bar));
        } while (v < target);
    }
    __syncthreads();
}

__global__ void __launch_bounds__(TPB, 1)
mega(const int* __restrict__ ht, const int* __restrict__ r_q,
     const int* __restrict__ r_tensor, const int* __restrict__ r_relative,
     const int* __restrict__ h_or_t,
     const float* __restrict__ rel_emb, const float* __restrict__ corr,
     const float* __restrict__ W_hh, const float* __restrict__ b_hh,
     const float* __restrict__ W_ht, const float* __restrict__ b_ht,
     const float* __restrict__ W_th, const float* __restrict__ b_th,
     const float* __restrict__ W_tt, const float* __restrict__ b_tt,
     const float* __restrict__ W_fin, const float* __restrict__ b_fin,
     const float* __restrict__ W_score, const float* __restrict__ b_score,
     int M, int nq, float* __restrict__ out) {
    const int tid  = threadIdx.x;
    const int gt   = blockIdx.x * TPB + tid;
    const int lane = tid & 31;
    const int gw   = gt >> 5;                  // global warp id

    // ---------- stage 0: zero g_acc, compute w_eff & ceff ----------
    for (int i = gt; i < NNODES; i += NT) g_acc[i] = make_float2(0.f, 0.f);
    if (gw < 256) {
        float v = 0.f;
#pragma unroll
        for (int i = 0; i < 4; i++) {
            int d = lane + 32 * i;
            v += W_fin[gw * D + d] * W_score[d];
        }
        v = warp_sum(v);
        if (lane == 0) { if (gw < D) g_w1[gw] = v; else g_w2[gw - D] = v; }
    } else if (gw == 256) {
        float v = 0.f;
#pragma unroll
        for (int i = 0; i < 4; i++) {
            int d = lane + 32 * i;
            v += b_fin[d] * W_score[d];
        }
        v = warp_sum(v);
        if (lane == 0) g_ceff = v + b_score[0];
    }
    grid_barrier();

    // ---------- stage 1: p_x = W_x @ w1, bdot = b_x · w1 ----------
    {
        const float* Ws[4] = {W_hh, W_ht, W_th, W_tt};
        const float* bs[4] = {b_hh, b_ht, b_th, b_tt};
        if (gw < 512) {
            int x = gw >> 7, k = gw & (D - 1);
            const float* row = Ws[x] + k * D;
            float v = 0.f;
#pragma unroll
            for (int i = 0; i < 4; i++) {
                int d = lane + 32 * i;
                v += row[d] * g_w1[d];
            }
            v = warp_sum(v);
            if (lane == 0) g_p[x][k] = v;
        } else if (gw < 516) {
            int x = gw - 512;
            float v = 0.f;
#pragma unroll
            for (int i = 0; i < 4; i++) {
                int d = lane + 32 * i;
                v += bs[x][d] * g_w1[d];
            }
            v = warp_sum(v);
            if (lane == 0) g_bdot[x] = v;
        }
    }
    grid_barrier();

    // ---------- stage 2: udot[r,x] = rel[r]·p_x, reldot[r] = rel[r]·w2 ----------
    if (gw < RREL) {
        int r = gw;
        float e0 = rel_emb[r * D + lane];
        float e1 = rel_emb[r * D + lane + 32];
        float e2 = rel_emb[r * D + lane + 64];
        float e3 = rel_emb[r * D + lane + 96];
#pragma unroll
        for (int x = 0; x < 5; x++) {
            const float* c = (x < 4) ? g_p[x] : g_w2;
            float v = e0 * c[lane] + e1 * c[lane + 32] + e2 * c[lane + 64] + e3 * c[lane + 96];
            v = warp_sum(v);
            if (lane == 0) {
                if (x < 4) g_udot[r * 4 + x] = v;
                else       g_reldot[r] = v;
            }
        }
    }
    grid_barrier();

    // ---------- stage 3: edges ----------
    {
        const int4* htp = (const int4*)ht;
        const int4* rtp = (const int4*)r_tensor;
        const int4* rqp = (const int4*)r_q;
        const int4* rrp = (const int4*)r_relative;
        const int4* hsp = (const int4*)h_or_t;
        const int ngroups = M >> 2;
        const int qg = nq >> 2;                // full query-only groups (nq%4==0 typical)

        // 3a: query edges — count only, no message, no attribute loads
        for (int g = gt; g < qg; g += NT) {
            int4 ev0 = htp[2 * g], ev1 = htp[2 * g + 1];
            int nd[8] = {ev0.x, ev0.y, ev0.z, ev0.w, ev1.x, ev1.y, ev1.z, ev1.w};
#pragma unroll
            for (int j = 0; j < 8; j++)
                asm volatile("red.global.add.f32 [%0], %1;"
                             :: "l"(&g_acc[nd[j]].y), "f"(1.0f) : "memory");
        }

        // 3b: remaining groups (boundary group handled by the < nq predicate)
        for (int g = qg + gt; g < ngroups; g += NT) {
            int4 ev0 = htp[2 * g], ev1 = htp[2 * g + 1];
            int4 rtv = rtp[g], rqv = rqp[g], rrv = rrp[g], hsv = hsp[g];
            int hh[4] = {ev0.x, ev0.z, ev1.x, ev1.z};
            int tt[4] = {ev0.y, ev0.w, ev1.y, ev1.w};
            int rta[4] = {rtv.x, rtv.y, rtv.z, rtv.w};
            int rqa[4] = {rqv.x, rqv.y, rqv.z, rqv.w};
            int rra[4] = {rrv.x, rrv.y, rrv.z, rrv.w};
            int hsa[4] = {hsv.x, hsv.y, hsv.z, hsv.w};
            int mbase = g << 2;
#pragma unroll
            for (int j = 0; j < 4; j++) {
                float c = corr[rta[j] * RREL + rqa[j]];
                float gate = 1.f / (1.f + __expf(-c));
                int idx = ((rra[j] == 0) ? 2 : 0) + ((hsa[j] == 0) ? 1 : 0);
                float s = gate * g_udot[rta[j] * 4 + idx] + g_bdot[idx];
                if (mbase + j < nq) s = 0.f;
                asm volatile("red.global.add.v2.f32 [%0], {%1, %2};"
                             :: "l"(&g_acc[hh[j]]), "f"(s), "f"(1.0f) : "memory");
                asm volatile("red.global.add.v2.f32 [%0], {%1, %2};"
                             :: "l"(&g_acc[tt[j]]), "f"(s), "f"(1.0f) : "memory");
            }
        }

        // tail (M not divisible by 4)
        for (int m = (ngroups << 2) + gt; m < M; m += NT) {
            int2 e = ((const int2*)ht)[m];
            int rt = r_tensor[m], rq = r_q[m];
            float c = corr[rt * RREL + rq];
            float gate = 1.f / (1.f + __expf(-c));
            int idx = ((r_relative[m] == 0) ? 2 : 0) + ((h_or_t[m] == 0) ? 1 : 0);
            float s = gate * g_udot[rt * 4 + idx] + g_bdot[idx];
            if (m < nq) s = 0.f;
            asm volatile("red.global.add.v2.f32 [%0], {%1, %2};"
                         :: "l"(&g_acc[e.x]), "f"(s), "f"(1.0f) : "memory");
            asm volatile("red.global.add.v2.f32 [%0], {%1, %2};"
                         :: "l"(&g_acc[e.y]), "f"(s), "f"(1.0f) : "memory");
        }
    }
    grid_barrier();

    // ---------- stage 4: queries ----------
    for (int q = gt; q < nq; q += NT) {
        int2 e = ((const int2*)ht)[q];
        float2 ah, at;
        ah.x = __ldcg(&g_acc[e.x].x); ah.y = __ldcg(&g_acc[e.x].y);
        at.x = __ldcg(&g_acc[e.y].x); at.y = __ldcg(&g_acc[e.y].y);
        out[q] = ah.x / fmaxf(ah.y, 1.f)
               + at.x / fmaxf(at.y, 1.f)
               + g_reldot[r_tensor[q]] + g_ceff;
    }
}

// ---------------- launch ----------------
extern "C" void kernel_launch(void* const* d_in, const int* in_sizes, int n_in,
                              void* d_out, int out_size) {
    const int* ht         = (const int*)d_in[0];
    const int* r_q        = (const int*)d_in[1];
    const int* r_tensor   = (const int*)d_in[2];
    const int* r_relative = (const int*)d_in[3];
    const int* h_or_t     = (const int*)d_in[4];
    int base = n_in - 14;
    const float* rel_emb = (const float*)d_in[base + 0];
    const float* corr    = (const float*)d_in[base + 1];
    const float* W_hh    = (const float*)d_in[base + 2];
    const float* b_hh    = (const float*)d_in[base + 3];
    const float* W_ht    = (const float*)d_in[base + 4];
    const float* b_ht    = (const float*)d_in[base + 5];
    const float* W_th    = (const float*)d_in[base + 6];
    const float* b_th    = (const float*)d_in[base + 7];
    const float* W_tt    = (const float*)d_in[base + 8];
    const float* b_tt    = (const float*)d_in[base + 9];
    const float* W_fin   = (const float*)d_in[base + 10];
    const float* b_fin   = (const float*)d_in[base + 11];
    const float* W_score = (const float*)d_in[base + 12];
    const float* b_score = (const float*)d_in[base + 13];

    int M  = in_sizes[0] / 2;
    int nq = out_size;

    mega<<<GRIDB, TPB>>>(ht, r_q, r_tensor, r_relative, h_or_t,
                         rel_emb, corr, W_hh, b_hh, W_ht, b_ht, W_th, b_th,
                         W_tt, b_tt, W_fin, b_fin, W_score, b_score,
                         M, nq, (float*)d_out);
}

// round 5
// speedup vs baseline: 1.3845x; 1.3845x over previous
#include <cuda_runtime.h>
#include <math.h>

#define D      128
#define RREL   500
#define NNODES 200000
#define PGB    148          // persistent pre-kernel grid
#define PTPB   256
#define PNT    (PGB * PTPB)

// ---------------- device scratch ----------------
__device__ float2 g_acc[NNODES];    // .x = sum(selected·w1), .y = message count
__device__ float  g_w1[D];
__device__ float  g_w2[D];
__device__ float  g_p[4][D];
__device__ float  g_bdot[4];
__device__ float  g_ceff;
__device__ float  g_udot[RREL * 4];
__device__ float  g_reldot[RREL];
__device__ unsigned g_bar;          // monotonic ticket counter (graph-replay safe)

__device__ __forceinline__ float warp_sum(float v) {
#pragma unroll
    for (int o = 16; o > 0; o >>= 1) v += __shfl_down_sync(0xffffffffu, v, o);
    return v;
}

__device__ __forceinline__ void grid_barrier() {
    __syncthreads();
    if (threadIdx.x == 0) {
        __threadfence();
        unsigned old = atomicAdd(&g_bar, 1u);
        unsigned target = old - (old % PGB) + PGB;
        unsigned v;
        do {
            asm volatile("ld.acquire.gpu.u32 %0, [%1];" : "=r"(v) : "l"(&g_bar));
        } while (v < target);
    }
    __syncthreads();
}

// ---------------- K1: all precompute + zeroing (persistent, 2 barriers) ----------------
__global__ void __launch_bounds__(PTPB)
k_pre(const float* __restrict__ rel_emb,
      const float* __restrict__ W_hh, const float* __restrict__ b_hh,
      const float* __restrict__ W_ht, const float* __restrict__ b_ht,
      const float* __restrict__ W_th, const float* __restrict__ b_th,
      const float* __restrict__ W_tt, const float* __restrict__ b_tt,
      const float* __restrict__ W_fin, const float* __restrict__ b_fin,
      const float* __restrict__ W_score, const float* __restrict__ b_score) {
    const int tid  = threadIdx.x;
    const int gt   = blockIdx.x * PTPB + tid;
    const int lane = tid & 31;
    const int gw   = gt >> 5;      // 0..1183

    // stage 0: w_eff & ceff (warps 0..256), zero g_acc (everyone)
    if (gw < 256) {
        float v = 0.f;
#pragma unroll
        for (int i = 0; i < 4; i++) {
            int d = lane + 32 * i;
            v += W_fin[gw * D + d] * W_score[d];
        }
        v = warp_sum(v);
        if (lane == 0) { if (gw < D) g_w1[gw] = v; else g_w2[gw - D] = v; }
    } else if (gw == 256) {
        float v = 0.f;
#pragma unroll
        for (int i = 0; i < 4; i++) {
            int d = lane + 32 * i;
            v += b_fin[d] * W_score[d];
        }
        v = warp_sum(v);
        if (lane == 0) g_ceff = v + b_score[0];
    }
    for (int i = gt; i < NNODES; i += PNT) g_acc[i] = make_float2(0.f, 0.f);
    grid_barrier();

    // stage 1: p_x = W_x @ w1, bdot
    {
        const float* Ws[4] = {W_hh, W_ht, W_th, W_tt};
        const float* bs[4] = {b_hh, b_ht, b_th, b_tt};
        if (gw < 512) {
            int x = gw >> 7, k = gw & (D - 1);
            const float* row = Ws[x] + k * D;
            float v = 0.f;
#pragma unroll
            for (int i = 0; i < 4; i++) {
                int d = lane + 32 * i;
                v += row[d] * g_w1[d];
            }
            v = warp_sum(v);
            if (lane == 0) g_p[x][k] = v;
        } else if (gw < 516) {
            int x = gw - 512;
            float v = 0.f;
#pragma unroll
            for (int i = 0; i < 4; i++) {
                int d = lane + 32 * i;
                v += bs[x][d] * g_w1[d];
            }
            v = warp_sum(v);
            if (lane == 0) g_bdot[x] = v;
        }
    }
    grid_barrier();

    // stage 2: udot / reldot (warp per relation)
    if (gw < RREL) {
        int r = gw;
        float e0 = rel_emb[r * D + lane];
        float e1 = rel_emb[r * D + lane + 32];
        float e2 = rel_emb[r * D + lane + 64];
        float e3 = rel_emb[r * D + lane + 96];
#pragma unroll
        for (int x = 0; x < 5; x++) {
            const float* c = (x < 4) ? g_p[x] : g_w2;
            float v = e0 * c[lane] + e1 * c[lane + 32] + e2 * c[lane + 64] + e3 * c[lane + 96];
            v = warp_sum(v);
            if (lane == 0) {
                if (x < 4) g_udot[r * 4 + x] = v;
                else       g_reldot[r] = v;
            }
        }
    }
}

// ---------------- K2: edges, 4 per thread, front-batched loads ----------------
__global__ void __launch_bounds__(256)
k_edge(const int* __restrict__ ht, const int* __restrict__ r_q,
       const int* __restrict__ r_tensor, const int* __restrict__ r_relative,
       const int* __restrict__ h_or_t, const float* __restrict__ corr,
       int M, int nq) {
    const int g = blockIdx.x * 256 + threadIdx.x;   // group of 4 edges
    const int ngroups = M >> 2;
    if (g < ngroups) {
        const int4* htp = (const int4*)ht;
        // 6 independent coalesced 16B loads, issued back-to-back
        int4 ev0 = htp[2 * g];
        int4 ev1 = htp[2 * g + 1];
        int4 rtv = ((const int4*)r_tensor)[g];
        int4 rqv = ((const int4*)r_q)[g];
        int4 rrv = ((const int4*)r_relative)[g];
        int4 hsv = ((const int4*)h_or_t)[g];
        int hh[4]  = {ev0.x, ev0.z, ev1.x, ev1.z};
        int tt[4]  = {ev0.y, ev0.w, ev1.y, ev1.w};
        int rta[4] = {rtv.x, rtv.y, rtv.z, rtv.w};
        int rqa[4] = {rqv.x, rqv.y, rqv.z, rqv.w};
        int rra[4] = {rrv.x, rrv.y, rrv.z, rrv.w};
        int hsa[4] = {hsv.x, hsv.y, hsv.z, hsv.w};
        // 4 independent gathers in flight
        float cv[4];
#pragma unroll
        for (int j = 0; j < 4; j++) cv[j] = __ldg(&corr[rta[j] * RREL + rqa[j]]);
        int mbase = g << 2;
#pragma unroll
        for (int j = 0; j < 4; j++) {
            float gate = 1.f / (1.f + __expf(-cv[j]));
            int idx = ((rra[j] == 0) ? 2 : 0) + ((hsa[j] == 0) ? 1 : 0);
            float s = gate * g_udot[rta[j] * 4 + idx] + g_bdot[idx];
            if (mbase + j < nq) s = 0.f;   // query edges: count only
            asm volatile("red.global.add.v2.f32 [%0], {%1, %2};"
                         :: "l"(&g_acc[hh[j]]), "f"(s), "f"(1.0f) : "memory");
            asm volatile("red.global.add.v2.f32 [%0], {%1, %2};"
                         :: "l"(&g_acc[tt[j]]), "f"(s), "f"(1.0f) : "memory");
        }
    }
    // tail: first (M & 3) threads of block 0
    int rem = M & 3;
    if (blockIdx.x == 0 && threadIdx.x < rem) {
        int m = (ngroups << 2) + threadIdx.x;
        int2 e = ((const int2*)ht)[m];
        int rt = r_tensor[m], rq = r_q[m];
        float c = corr[rt * RREL + rq];
        float gate = 1.f / (1.f + __expf(-c));
        int idx = ((r_relative[m] == 0) ? 2 : 0) + ((h_or_t[m] == 0) ? 1 : 0);
        float s = gate * g_udot[rt * 4 + idx] + g_bdot[idx];
        if (m < nq) s = 0.f;
        asm volatile("red.global.add.v2.f32 [%0], {%1, %2};"
                     :: "l"(&g_acc[e.x]), "f"(s), "f"(1.0f) : "memory");
        asm volatile("red.global.add.v2.f32 [%0], {%1, %2};"
                     :: "l"(&g_acc[e.y]), "f"(s), "f"(1.0f) : "memory");
    }
}

// ---------------- K3: queries ----------------
__global__ void __launch_bounds__(256)
k_query(const int* __restrict__ ht, const int* __restrict__ r_tensor,
        float* __restrict__ out, int nq) {
    int q = blockIdx.x * 256 + threadIdx.x;
    if (q >= nq) return;
    int2 e = ((const int2*)ht)[q];
    float2 ah = g_acc[e.x];
    float2 at = g_acc[e.y];
    out[q] = ah.x / fmaxf(ah.y, 1.f)
           + at.x / fmaxf(at.y, 1.f)
           + g_reldot[r_tensor[q]] + g_ceff;
}

// ---------------- launch ----------------
extern "C" void kernel_launch(void* const* d_in, const int* in_sizes, int n_in,
                              void* d_out, int out_size) {
    const int* ht         = (const int*)d_in[0];
    const int* r_q        = (const int*)d_in[1];
    const int* r_tensor   = (const int*)d_in[2];
    const int* r_relative = (const int*)d_in[3];
    const int* h_or_t     = (const int*)d_in[4];
    int base = n_in - 14;
    const float* rel_emb = (const float*)d_in[base + 0];
    const float* corr    = (const float*)d_in[base + 1];
    const float* W_hh    = (const float*)d_in[base + 2];
    const float* b_hh    = (const float*)d_in[base + 3];
    const float* W_ht    = (const float*)d_in[base + 4];
    const float* b_ht    = (const float*)d_in[base + 5];
    const float* W_th    = (const float*)d_in[base + 6];
    const float* b_th    = (const float*)d_in[base + 7];
    const float* W_tt    = (const float*)d_in[base + 8];
    const float* b_tt    = (const float*)d_in[base + 9];
    const float* W_fin   = (const float*)d_in[base + 10];
    const float* b_fin   = (const float*)d_in[base + 11];
    const float* W_score = (const float*)d_in[base + 12];
    const float* b_score = (const float*)d_in[base + 13];

    int M  = in_sizes[0] / 2;
    int nq = out_size;

    k_pre<<<PGB, PTPB>>>(rel_emb, W_hh, b_hh, W_ht, b_ht, W_th, b_th,
                         W_tt, b_tt, W_fin, b_fin, W_score, b_score);
    int ngroups = M >> 2;
    k_edge<<<(ngroups + 255) / 256, 256>>>(ht, r_q, r_tensor, r_relative,
                                           h_or_t, corr, M, nq);
    k_query<<<(nq + 255) / 256, 256>>>(ht, r_tensor, (float*)d_out, nq);
}